// round 6
// baseline (speedup 1.0000x reference)
#include <cuda_runtime.h>

#define BN   8
#define CN   64
#define HN   256
#define WN   256
#define HP   257
#define WP   257
#define HWN  (HN * WN)          // 65536
#define NPIX (HP * WP)          // 66049
#define LN_EPS 1e-5f
#define NEG_SLOPE 0.01f

// Padded xs plane: logical xs(i,j), i,j in [0,257), stored at [(i+2),(j+2)]
// in a 261-row x 264-stride plane with zero border -> taps need no bounds checks.
#define HPP  261
#define WPP  261
#define WST  264
#define NPAD (HPP * WST)

#define NBLK   65               // ceil(66049/1024) blocks per image
#define NGRID  (NBLK * BN)      // 520 blocks total in fused kernel

// Scratch (static device globals — allowed)
__device__ float g_cs [BN * HWN];         // channel sum          [8,256,256]
__device__ float g_xsp[BN * NPAD];        // padded pooled sum
__device__ float g_part[BN * NBLK * 2];   // per-block (sum, sumsq)
__device__ unsigned int g_ctr;            // grid-barrier arrival counter

// ---------------------------------------------------------------------------
// 1) Channel sum, float4 vectorized. 2048 blocks x 64 threads (wave balance).
// ---------------------------------------------------------------------------
__global__ void k_chansum(const float* __restrict__ x) {
    int t = blockIdx.x * 64 + threadIdx.x;           // [0, BN*HWN/4)
    const int Q = HWN / 4;                            // 16384 float4 per plane
    int b  = t / Q;
    int p4 = t - b * Q;
    const float4* xp = reinterpret_cast<const float4*>(x) + (size_t)b * CN * Q + p4;
    float ax = 0.f, ay = 0.f, az = 0.f, aw = 0.f;
#pragma unroll 16
    for (int c = 0; c < CN; ++c) {
        float4 v = __ldg(xp + (size_t)c * Q);
        ax += v.x; ay += v.y; az += v.z; aw += v.w;
    }
    reinterpret_cast<float4*>(g_cs)[t] = make_float4(ax, ay, az, aw);
}

// ---------------------------------------------------------------------------
// 2) avg_pool2d(k=2,s=1,p=1,count_include_pad) -> padded xs plane.
//    Also resets the grid-barrier counter for the fused kernel (stream order
//    guarantees this lands before k_fused starts; re-done every call so the
//    captured graph replays identically).
// ---------------------------------------------------------------------------
__global__ void k_pool() {
    int t = blockIdx.x * blockDim.x + threadIdx.x;
    if (t == 0) g_ctr = 0;
    const int NP = HPP * WPP;
    if (t >= BN * NP) return;
    int b = t / NP;
    int p = t - b * NP;
    int pi = p / WPP;
    int pj = p - pi * WPP;
    int i = pi - 2, j = pj - 2;                       // xs coords

    float v = 0.f;
    if ((unsigned)i < (unsigned)HP && (unsigned)j < (unsigned)WP) {
        const float* cs = g_cs + (size_t)b * HWN;
        float s = 0.f;
        int r0 = i - 1, c0 = j - 1;
        bool vr0 = (unsigned)r0 < (unsigned)HN, vr1 = (unsigned)i < (unsigned)HN;
        bool vc0 = (unsigned)c0 < (unsigned)WN, vc1 = (unsigned)j < (unsigned)WN;
        if (vr0) {
            const float* row = cs + r0 * WN;
            if (vc0) s += row[c0];
            if (vc1) s += row[j];
        }
        if (vr1) {
            const float* row = cs + i * WN;
            if (vc0) s += row[c0];
            if (vc1) s += row[j];
        }
        v = s * 0.25f;
    }
    g_xsp[(size_t)b * NPAD + pi * WST + pj] = v;
}

// ---------------------------------------------------------------------------
// 3) Fused: 16-tap stencil + bias  ->  grid barrier  ->  LN stats + normalize
//    + LeakyReLU.  Grid (NBLK, BN) = 520 blocks x 256 threads — single wave
//    (well under residency capacity), so the spin barrier is deadlock-free.
//    Feature values live in registers across the barrier: no g_y buffer.
// ---------------------------------------------------------------------------
__global__ void __launch_bounds__(256)
k_fused(const float* __restrict__ cw, const float* __restrict__ cb,
        float* __restrict__ out) {
    __shared__ float s_w[8];
    __shared__ float s_red[8][2];
    const int tid = threadIdx.x;
    const int b   = blockIdx.y;
    if (tid < 8) s_w[tid] = cw[tid];
    __syncthreads();
    const float bias = __ldg(cb);

    const float* __restrict__ xs = g_xsp + (size_t)b * NPAD;

    float v0 = 0.f, v1 = 0.f, v2 = 0.f, v3 = 0.f;
    float lsum = 0.f, lsq = 0.f;
    int pbase = blockIdx.x * 1024 + tid;

    {
        float* vv[4] = {&v0, &v1, &v2, &v3};
#pragma unroll
        for (int k = 0; k < 4; ++k) {
            int p = pbase + k * 256;
            if (p < NPIX) {
                int h  = p / WP;
                int wi = p - h * WP;
                const float* c = xs + (h + 2) * WST + (wi + 2);
                float v = bias;
                v += s_w[0] * (__ldg(c + 2 * WST + 2) - __ldg(c - 2 * WST - 2));
                v += s_w[1] * (__ldg(c + 2 * WST + 1) - __ldg(c - 2 * WST - 1));
                v += s_w[2] * (__ldg(c + 2 * WST    ) - __ldg(c - 2 * WST    ));
                v += s_w[3] * (__ldg(c + 2 * WST - 1) - __ldg(c - 2 * WST + 1));
                v += s_w[4] * (__ldg(c + 2 * WST - 2) - __ldg(c - 2 * WST + 2));
                v += s_w[5] * (__ldg(c + 1 * WST - 2) - __ldg(c - 1 * WST + 2));
                v += s_w[6] * (__ldg(c           - 2) - __ldg(c           + 2));
                v += s_w[7] * (__ldg(c - 1 * WST - 2) - __ldg(c + 1 * WST + 2));
                *vv[k] = v;
                lsum += v;
                lsq  += v * v;
            }
        }
    }

    // Deterministic block reduction: warp shuffles, then ordered combine.
#pragma unroll
    for (int o = 16; o > 0; o >>= 1) {
        lsum += __shfl_down_sync(0xffffffffu, lsum, o);
        lsq  += __shfl_down_sync(0xffffffffu, lsq,  o);
    }
    int wid = tid >> 5, lane = tid & 31;
    if (lane == 0) { s_red[wid][0] = lsum; s_red[wid][1] = lsq; }
    __syncthreads();
    if (tid == 0) {
        float a = 0.f, q = 0.f;
#pragma unroll
        for (int w = 0; w < 8; ++w) { a += s_red[w][0]; q += s_red[w][1]; }
        g_part[(b * NBLK + blockIdx.x) * 2 + 0] = a;
        g_part[(b * NBLK + blockIdx.x) * 2 + 1] = q;
        __threadfence();                               // publish partials
        atomicAdd(&g_ctr, 1u);                         // arrive
    }

    // Grid barrier: single wave -> all blocks resident -> spin is safe.
    if (tid == 0) {
        volatile unsigned int* ctr = &g_ctr;
        while (*ctr < (unsigned)NGRID) { }
    }
    __syncthreads();
    __threadfence();                                   // acquire partials

    // Redundant per-block stats (fixed order -> deterministic, L2-resident).
    const float* __restrict__ part = g_part + b * NBLK * 2;
    float a = 0.f, q = 0.f;
#pragma unroll 13
    for (int i = 0; i < NBLK; ++i) {
        a += part[i * 2 + 0];
        q += part[i * 2 + 1];
    }
    const float inv_n = 1.0f / (float)NPIX;
    const float mean = a * inv_n;
    const float istd = rsqrtf(q * inv_n - mean * mean + LN_EPS);

    float* __restrict__ o = out + (size_t)b * NPIX;
    {
        float vv[4] = {v0, v1, v2, v3};
#pragma unroll
        for (int k = 0; k < 4; ++k) {
            int p = pbase + k * 256;
            if (p < NPIX) {
                float v = (vv[k] - mean) * istd;
                o[p] = v >= 0.f ? v : NEG_SLOPE * v;
            }
        }
    }
}

// ---------------------------------------------------------------------------

extern "C" void kernel_launch(void* const* d_in, const int* in_sizes, int n_in,
                              void* d_out, int out_size) {
    const float* x  = (const float*)d_in[0];   // [8,64,256,256]
    const float* cw = (const float*)d_in[1];   // [1,8]
    const float* cb = (const float*)d_in[2];   // [1]
    float* out = (float*)d_out;                // [8,1,257,257]
    (void)in_sizes; (void)n_in; (void)out_size;

    k_chansum<<<2048, 64>>>(x);

    int n_pad = BN * HPP * WPP;
    k_pool<<<(n_pad + 255) / 256, 256>>>();

    dim3 gfused(NBLK, BN);
    k_fused<<<gfused, 256>>>(cw, cb, out);
}